// round 15
// baseline (speedup 1.0000x reference)
#include <cuda_runtime.h>
#include <cuda_bf16.h>
#include <math_constants.h>

#define BATCH 4
#define SEQ   2048
#define CH    256
#define HEADS 8
#define DH    32
#define BH    (BATCH*HEADS)
#define M_ROWS (BATCH*SEQ)

typedef unsigned int u32;

// ---------------------------------------------------------------------------
// Scratch (fp32, tf32-rounded values)
// ---------------------------------------------------------------------------
__device__ float g_xr[M_ROWS * CH];
__device__ float g_wqr[768 * CH];
__device__ float g_wpr[CH * CH];
__device__ float g_q[BH * SEQ * DH];
__device__ float g_k[BH * SEQ * DH];
__device__ float g_v[BH * DH * SEQ];    // transposed [bh][dh][seq]
__device__ float g_att[M_ROWS * CH];

// ---------------------------------------------------------------------------
// tf32 helpers
// ---------------------------------------------------------------------------
__device__ __forceinline__ float tf32f(float x) {
    u32 r; asm("cvt.rna.tf32.f32 %0,%1;" : "=r"(r) : "f"(x));
    return __uint_as_float(r);
}
__device__ __forceinline__ void mma_tf32(float* d, const float* a, float b0, float b1) {
    asm volatile(
        "mma.sync.aligned.m16n8k8.row.col.f32.tf32.tf32.f32 "
        "{%0,%1,%2,%3},{%4,%5,%6,%7},{%8,%9},{%0,%1,%2,%3};"
        : "+f"(d[0]), "+f"(d[1]), "+f"(d[2]), "+f"(d[3])
        : "r"(__float_as_uint(a[0])), "r"(__float_as_uint(a[1])),
          "r"(__float_as_uint(a[2])), "r"(__float_as_uint(a[3])),
          "r"(__float_as_uint(b0)), "r"(__float_as_uint(b1)));
}

// Mask: lengths in [1,2048]; int64 vs int32 sniff (word[1]==0 => int64).
__device__ __forceinline__ int read_len(const void* kpm, int b)
{
    const int* p32 = (const int*)kpm;
    int len = (p32[1] == 0) ? (int)((const long long*)kpm)[b] : p32[b];
    if (len < 1)   len = 1;
    if (len > SEQ) len = SEQ;
    return len;
}

// ---------------------------------------------------------------------------
// Round fp32 -> tf32-valued fp32, vectorized x4.
// ---------------------------------------------------------------------------
__global__ void round_kernel(const float* __restrict__ src,
                             float* __restrict__ dst, int n4)
{
    const int i = blockIdx.x * blockDim.x + threadIdx.x;
    if (i >= n4) return;
    float4 v = ((const float4*)src)[i];
    v.x = tf32f(v.x); v.y = tf32f(v.y); v.z = tf32f(v.z); v.w = tf32f(v.w);
    ((float4*)dst)[i] = v;
}

// ---------------------------------------------------------------------------
// TF32 NT GEMM (validated R12/R14): block 128x128, 8 warps, warp tile 32x64.
// ---------------------------------------------------------------------------
#define AST 36

struct QkvEpi {
    __device__ __forceinline__ void operator()(int m, int n, float val) const {
        const int b  = m >> 11;
        const int nq = m & 2047;
        const int s  = n >> 8;        // 0=q 1=k 2=v
        const int h  = (n >> 5) & 7;
        const int d  = n & 31;
        const float rv = tf32f(val);
        const size_t bh = (size_t)(b * 8 + h);
        if (s == 0)      g_q[(bh * SEQ + nq) * DH + d] = rv;
        else if (s == 1) g_k[(bh * SEQ + nq) * DH + d] = rv;
        else             g_v[(bh * DH + d) * SEQ + nq] = rv;   // transposed
    }
};

struct ProjEpi {
    float* out;
    const float* bias;
    __device__ __forceinline__ void operator()(int m, int n, float val) const {
        out[(size_t)m * CH + n] = val + bias[n];
    }
};

template <typename Epi>
__device__ __forceinline__ void mma_gemm(
    const float* __restrict__ A, const float* __restrict__ B,
    int bm, int bn, const Epi& epi)
{
    __shared__ __align__(16) float sA[128][AST];
    __shared__ __align__(16) float sB[128][AST];

    const int tid  = threadIdx.x;
    const int warp = tid >> 5, lane = tid & 31;
    const int g = lane >> 2, tq = lane & 3, t2 = tq * 2;
    const int wm = warp >> 1, wn = warp & 1;

    float acc[2][8][4];
#pragma unroll
    for (int mf = 0; mf < 2; mf++)
#pragma unroll
        for (int nf = 0; nf < 8; nf++)
#pragma unroll
            for (int r = 0; r < 4; r++) acc[mf][nf][r] = 0.f;

    for (int ks = 0; ks < 8; ks++) {
        const int k0 = ks * 32;
        __syncthreads();
#pragma unroll
        for (int i = 0; i < 4; i++) {
            const int idx = tid + i * 256;
            const int row = idx >> 3;
            const int c   = (idx & 7) * 4;
            *(float4*)&sA[row][c] = *(const float4*)&A[(size_t)(bm + row) * 256 + k0 + c];
            *(float4*)&sB[row][c] = *(const float4*)&B[(size_t)(bn + row) * 256 + k0 + c];
        }
        __syncthreads();

#pragma unroll
        for (int s = 0; s < 4; s++) {
            float a[2][4];
#pragma unroll
            for (int mf = 0; mf < 2; mf++) {
                const int rb = wm * 32 + mf * 16;
                a[mf][0] = sA[rb + g    ][s*8 + tq];
                a[mf][1] = sA[rb + g + 8][s*8 + tq];
                a[mf][2] = sA[rb + g    ][s*8 + tq + 4];
                a[mf][3] = sA[rb + g + 8][s*8 + tq + 4];
            }
#pragma unroll
            for (int nf = 0; nf < 8; nf++) {
                const int nb = wn * 64 + nf * 8 + g;
                const float b0 = sB[nb][s*8 + tq];
                const float b1 = sB[nb][s*8 + tq + 4];
#pragma unroll
                for (int mf = 0; mf < 2; mf++)
                    mma_tf32(acc[mf][nf], a[mf], b0, b1);
            }
        }
    }

#pragma unroll
    for (int mf = 0; mf < 2; mf++) {
        const int r0 = bm + wm * 32 + mf * 16 + g;
#pragma unroll
        for (int nf = 0; nf < 8; nf++) {
            const int c0 = bn + wn * 64 + nf * 8 + t2;
            epi(r0,     c0,     acc[mf][nf][0]);
            epi(r0,     c0 + 1, acc[mf][nf][1]);
            epi(r0 + 8, c0,     acc[mf][nf][2]);
            epi(r0 + 8, c0 + 1, acc[mf][nf][3]);
        }
    }
}

__global__ __launch_bounds__(256) void qkv_mma_kernel()
{
    QkvEpi epi;
    mma_gemm(g_xr, g_wqr, blockIdx.x * 128, blockIdx.y * 128, epi);
}

__global__ __launch_bounds__(256) void proj_mma_kernel(
    float* __restrict__ out, const float* __restrict__ bias)
{
    ProjEpi epi{out, bias};
    mma_gemm(g_att, g_wpr, blockIdx.x * 128, blockIdx.y * 128, epi);
}

// ---------------------------------------------------------------------------
// TF32 flash attention: 4 warps x 16 q-rows, 128-key tiles, exp2 softmax.
// PV P-operand staged through per-warp smem (no shuffles).
// ---------------------------------------------------------------------------
#define KTILE 128
#define KST 36    // sK row stride (floats)
#define VST 132   // sV row stride (floats)
#define PST 40    // sP row stride: banks (8g+tq)%32, conflict-free

__global__ __launch_bounds__(128) void attn_kernel(const void* __restrict__ kpm)
{
    __shared__ __align__(16) float sK[KTILE][KST];  // [key][dh]
    __shared__ __align__(16) float sV[32][VST];     // [dh][key]
    __shared__ __align__(16) float sP[4][16][PST];  // per-warp P staging (32-key chunk)

    const int bh = blockIdx.y;
    const int b  = bh >> 3;
    const int h  = bh & 7;
    const int tid  = threadIdx.x;
    const int warp = tid >> 5;
    const int lane = tid & 31;
    const int g  = lane >> 2;
    const int tq = lane & 3;
    const int t2 = tq * 2;
    const int r0 = blockIdx.x * 64 + warp * 16;

    const int len = read_len(kpm, b);
    const float scale2 = 0.17677669529663687f * 1.4426950408889634f;  // /sqrt(dh)*log2(e)

    float q[4][4];
    {
        const float* qb = g_q + ((size_t)bh * SEQ + r0) * DH;
#pragma unroll
        for (int s = 0; s < 4; s++) {
            q[s][0] = qb[(size_t)g * DH       + s*8 + tq];
            q[s][1] = qb[(size_t)(g+8) * DH   + s*8 + tq];
            q[s][2] = qb[(size_t)g * DH       + s*8 + tq + 4];
            q[s][3] = qb[(size_t)(g+8) * DH   + s*8 + tq + 4];
        }
    }

    float O[4][4];
#pragma unroll
    for (int i = 0; i < 4; i++)
#pragma unroll
        for (int j = 0; j < 4; j++) O[i][j] = 0.f;
    float m0 = -CUDART_INF_F, m1 = -CUDART_INF_F;
    float l0 = 0.f, l1 = 0.f;

    const int ntiles = (len + KTILE - 1) >> 7;
    for (int kt = 0; kt < ntiles; kt++) {
        const int k0 = kt * KTILE;
        __syncthreads();
        {
            const float* gk = g_k + ((size_t)bh * SEQ + k0) * DH;
            const float* gv = g_v + (size_t)bh * DH * SEQ + k0;
#pragma unroll
            for (int it = 0; it < 8; it++) {
                const int idx = tid + it * 128;        // 0..1023
                const int krr = idx >> 3, kc = (idx & 7) * 4;
                *(float4*)&sK[krr][kc] = *(const float4*)(gk + (size_t)krr * DH + kc);
                const int vrr = idx >> 5, vc = (idx & 31) * 4;
                *(float4*)&sV[vrr][vc] = *(const float4*)(gv + (size_t)vrr * SEQ + vc);
            }
        }
        __syncthreads();

        // ---- S = Q K^T (16 x 128) ----
        float S[16][4];
#pragma unroll
        for (int nt = 0; nt < 16; nt++) {
            float* s = S[nt];
            s[0] = s[1] = s[2] = s[3] = 0.f;
            const int key = nt * 8 + g;
#pragma unroll
            for (int ss = 0; ss < 4; ss++) {
                const float b0 = sK[key][ss*8 + tq];
                const float b1 = sK[key][ss*8 + tq + 4];
                mma_tf32(s, q[ss], b0, b1);
            }
        }

        // ---- scale (log2 domain) + mask ----
#pragma unroll
        for (int nt = 0; nt < 16; nt++) {
            const int kcol = k0 + nt * 8 + t2;
            const bool v0 = kcol < len, v1 = (kcol + 1) < len;
            S[nt][0] = v0 ? S[nt][0] * scale2 : -CUDART_INF_F;
            S[nt][1] = v1 ? S[nt][1] * scale2 : -CUDART_INF_F;
            S[nt][2] = v0 ? S[nt][2] * scale2 : -CUDART_INF_F;
            S[nt][3] = v1 ? S[nt][3] * scale2 : -CUDART_INF_F;
        }

        // ---- online softmax (rows g, g+8), exp2 domain ----
        float rm0 = -CUDART_INF_F, rm1 = -CUDART_INF_F;
#pragma unroll
        for (int nt = 0; nt < 16; nt++) {
            rm0 = fmaxf(rm0, fmaxf(S[nt][0], S[nt][1]));
            rm1 = fmaxf(rm1, fmaxf(S[nt][2], S[nt][3]));
        }
        rm0 = fmaxf(rm0, __shfl_xor_sync(0xffffffffu, rm0, 1));
        rm0 = fmaxf(rm0, __shfl_xor_sync(0xffffffffu, rm0, 2));
        rm1 = fmaxf(rm1, __shfl_xor_sync(0xffffffffu, rm1, 1));
        rm1 = fmaxf(rm1, __shfl_xor_sync(0xffffffffu, rm1, 2));

        const float nm0 = fmaxf(m0, rm0), nm1 = fmaxf(m1, rm1);
        const float cr0 = exp2f(m0 - nm0), cr1 = exp2f(m1 - nm1);
        m0 = nm0; m1 = nm1;
        l0 *= cr0; l1 *= cr1;
#pragma unroll
        for (int dn = 0; dn < 4; dn++) {
            O[dn][0] *= cr0; O[dn][1] *= cr0;
            O[dn][2] *= cr1; O[dn][3] *= cr1;
        }

        float ps0 = 0.f, ps1 = 0.f;
#pragma unroll
        for (int nt = 0; nt < 16; nt++) {
            S[nt][0] = exp2f(S[nt][0] - m0);
            S[nt][1] = exp2f(S[nt][1] - m0);
            S[nt][2] = exp2f(S[nt][2] - m1);
            S[nt][3] = exp2f(S[nt][3] - m1);
            ps0 += S[nt][0] + S[nt][1];
            ps1 += S[nt][2] + S[nt][3];
        }
        ps0 += __shfl_xor_sync(0xffffffffu, ps0, 1);
        ps0 += __shfl_xor_sync(0xffffffffu, ps0, 2);
        ps1 += __shfl_xor_sync(0xffffffffu, ps1, 1);
        ps1 += __shfl_xor_sync(0xffffffffu, ps1, 2);
        l0 += ps0; l1 += ps1;

        // ---- O += P V : stage P through per-warp smem in 32-key chunks ----
        float (*Pw)[PST] = sP[warp];
#pragma unroll
        for (int ch = 0; ch < 4; ch++) {
#pragma unroll
            for (int j = 0; j < 4; j++) {
                const int nt = ch * 4 + j;
                *(float2*)&Pw[g    ][j*8 + t2] = make_float2(S[nt][0], S[nt][1]);
                *(float2*)&Pw[g + 8][j*8 + t2] = make_float2(S[nt][2], S[nt][3]);
            }
            __syncwarp();
#pragma unroll
            for (int j = 0; j < 4; j++) {
                const int ss = ch * 4 + j;
                float a[4];
                a[0] = tf32f(Pw[g    ][j*8 + tq]);
                a[1] = tf32f(Pw[g + 8][j*8 + tq]);
                a[2] = tf32f(Pw[g    ][j*8 + tq + 4]);
                a[3] = tf32f(Pw[g + 8][j*8 + tq + 4]);
#pragma unroll
                for (int dn = 0; dn < 4; dn++) {
                    const float b0 = sV[dn*8 + g][ss*8 + tq];
                    const float b1 = sV[dn*8 + g][ss*8 + tq + 4];
                    mma_tf32(O[dn], a, b0, b1);
                }
            }
            __syncwarp();
        }
    }

    // ---- normalize + store (tf32-rounded for the proj GEMM) ----
    const float inv0 = 1.f / l0, inv1 = 1.f / l1;
    const int row0 = r0 + g, row1 = r0 + g + 8;
#pragma unroll
    for (int dn = 0; dn < 4; dn++) {
        const int col = h * 32 + dn * 8 + t2;
        const size_t i0 = ((size_t)(b * SEQ + row0)) * CH + col;
        const size_t i1 = ((size_t)(b * SEQ + row1)) * CH + col;
        g_att[i0]     = tf32f(O[dn][0] * inv0);
        g_att[i0 + 1] = tf32f(O[dn][1] * inv0);
        g_att[i1]     = tf32f(O[dn][2] * inv1);
        g_att[i1 + 1] = tf32f(O[dn][3] * inv1);
    }
}

// ---------------------------------------------------------------------------
// Launch
// ---------------------------------------------------------------------------
extern "C" void kernel_launch(void* const* d_in, const int* in_sizes, int n_in,
                              void* d_out, int out_size)
{
    (void)out_size;
    const float* x = nullptr; const void* kpm = nullptr;
    const float* w_qkv = nullptr; const float* w_proj = nullptr;
    const float* b_proj = nullptr;

    for (int i = 0; i < n_in; i++) {
        switch (in_sizes[i]) {
            case 2097152: x      = (const float*)d_in[i]; break;
            case 4:       kpm    = d_in[i];               break;
            case 196608:  w_qkv  = (const float*)d_in[i]; break;
            case 65536:   w_proj = (const float*)d_in[i]; break;
            case 256:     b_proj = (const float*)d_in[i]; break;
            default: break;
        }
    }
    float* out = (float*)d_out;

    float *xr, *wqr, *wpr;
    cudaGetSymbolAddress((void**)&xr,  g_xr);
    cudaGetSymbolAddress((void**)&wqr, g_wqr);
    cudaGetSymbolAddress((void**)&wpr, g_wpr);

    round_kernel<<<(2097152/4 + 255)/256, 256>>>(x, xr, 2097152/4);
    round_kernel<<<(196608/4  + 255)/256, 256>>>(w_qkv, wqr, 196608/4);
    round_kernel<<<(65536/4   + 255)/256, 256>>>(w_proj, wpr, 65536/4);

    {   // QKV mma: 8192 x 768
        dim3 grid(M_ROWS / 128, 768 / 128);
        qkv_mma_kernel<<<grid, 256>>>();
    }
    {   // attention: 64 q-rows per block, 128-key tiles
        dim3 grid(SEQ / 64, BH);
        attn_kernel<<<grid, 128>>>(kpm);
    }
    {   // proj mma: 8192 x 256
        dim3 grid(M_ROWS / 128, 256 / 128);
        proj_mma_kernel<<<grid, 256>>>(out, b_proj);
    }
}

// round 16
// speedup vs baseline: 1.1429x; 1.1429x over previous
#include <cuda_runtime.h>
#include <cuda_bf16.h>
#include <math_constants.h>

#define BATCH 4
#define SEQ   2048
#define CH    256
#define HEADS 8
#define DH    32
#define BH    (BATCH*HEADS)
#define M_ROWS (BATCH*SEQ)

typedef unsigned int u32;

// ---------------------------------------------------------------------------
// Scratch (fp32, tf32-rounded values)
// ---------------------------------------------------------------------------
__device__ float g_q[BH * SEQ * DH];
__device__ float g_k[BH * SEQ * DH];
__device__ float g_v[BH * DH * SEQ];    // transposed [bh][dh][seq]
__device__ float g_att[M_ROWS * CH];

// ---------------------------------------------------------------------------
// tf32 helpers
// ---------------------------------------------------------------------------
__device__ __forceinline__ float tf32f(float x) {
    u32 r; asm("cvt.rna.tf32.f32 %0,%1;" : "=r"(r) : "f"(x));
    return __uint_as_float(r);
}
__device__ __forceinline__ void mma_tf32(float* d, const float* a, float b0, float b1) {
    asm volatile(
        "mma.sync.aligned.m16n8k8.row.col.f32.tf32.tf32.f32 "
        "{%0,%1,%2,%3},{%4,%5,%6,%7},{%8,%9},{%0,%1,%2,%3};"
        : "+f"(d[0]), "+f"(d[1]), "+f"(d[2]), "+f"(d[3])
        : "r"(__float_as_uint(a[0])), "r"(__float_as_uint(a[1])),
          "r"(__float_as_uint(a[2])), "r"(__float_as_uint(a[3])),
          "r"(__float_as_uint(b0)), "r"(__float_as_uint(b1)));
}

// Mask: lengths in [1,2048]; int64 vs int32 sniff (word[1]==0 => int64).
__device__ __forceinline__ int read_len(const void* kpm, int b)
{
    const int* p32 = (const int*)kpm;
    int len = (p32[1] == 0) ? (int)((const long long*)kpm)[b] : p32[b];
    if (len < 1)   len = 1;
    if (len > SEQ) len = SEQ;
    return len;
}

// ---------------------------------------------------------------------------
// TF32 NT GEMM (validated R12/R14) with tf32 rounding folded into g2s.
// Block 128x128, 8 warps, warp tile 32x64.
// ---------------------------------------------------------------------------
#define AST 36

struct QkvEpi {
    __device__ __forceinline__ void operator()(int m, int n, float val) const {
        const int b  = m >> 11;
        const int nq = m & 2047;
        const int s  = n >> 8;        // 0=q 1=k 2=v
        const int h  = (n >> 5) & 7;
        const int d  = n & 31;
        const float rv = tf32f(val);
        const size_t bh = (size_t)(b * 8 + h);
        if (s == 0)      g_q[(bh * SEQ + nq) * DH + d] = rv;
        else if (s == 1) g_k[(bh * SEQ + nq) * DH + d] = rv;
        else             g_v[(bh * DH + d) * SEQ + nq] = rv;   // transposed
    }
};

struct ProjEpi {
    float* out;
    const float* bias;
    __device__ __forceinline__ void operator()(int m, int n, float val) const {
        out[(size_t)m * CH + n] = val + bias[n];
    }
};

template <typename Epi>
__device__ __forceinline__ void mma_gemm(
    const float* __restrict__ A, const float* __restrict__ B,
    int bm, int bn, const Epi& epi)
{
    __shared__ __align__(16) float sA[128][AST];
    __shared__ __align__(16) float sB[128][AST];

    const int tid  = threadIdx.x;
    const int warp = tid >> 5, lane = tid & 31;
    const int g = lane >> 2, tq = lane & 3, t2 = tq * 2;
    const int wm = warp >> 1, wn = warp & 1;

    float acc[2][8][4];
#pragma unroll
    for (int mf = 0; mf < 2; mf++)
#pragma unroll
        for (int nf = 0; nf < 8; nf++)
#pragma unroll
            for (int r = 0; r < 4; r++) acc[mf][nf][r] = 0.f;

    for (int ks = 0; ks < 8; ks++) {
        const int k0 = ks * 32;
        __syncthreads();
#pragma unroll
        for (int i = 0; i < 4; i++) {
            const int idx = tid + i * 256;
            const int row = idx >> 3;
            const int c   = (idx & 7) * 4;
            float4 va = *(const float4*)&A[(size_t)(bm + row) * 256 + k0 + c];
            float4 vb = *(const float4*)&B[(size_t)(bn + row) * 256 + k0 + c];
            va.x = tf32f(va.x); va.y = tf32f(va.y); va.z = tf32f(va.z); va.w = tf32f(va.w);
            vb.x = tf32f(vb.x); vb.y = tf32f(vb.y); vb.z = tf32f(vb.z); vb.w = tf32f(vb.w);
            *(float4*)&sA[row][c] = va;
            *(float4*)&sB[row][c] = vb;
        }
        __syncthreads();

#pragma unroll
        for (int s = 0; s < 4; s++) {
            float a[2][4];
#pragma unroll
            for (int mf = 0; mf < 2; mf++) {
                const int rb = wm * 32 + mf * 16;
                a[mf][0] = sA[rb + g    ][s*8 + tq];
                a[mf][1] = sA[rb + g + 8][s*8 + tq];
                a[mf][2] = sA[rb + g    ][s*8 + tq + 4];
                a[mf][3] = sA[rb + g + 8][s*8 + tq + 4];
            }
#pragma unroll
            for (int nf = 0; nf < 8; nf++) {
                const int nb = wn * 64 + nf * 8 + g;
                const float b0 = sB[nb][s*8 + tq];
                const float b1 = sB[nb][s*8 + tq + 4];
#pragma unroll
                for (int mf = 0; mf < 2; mf++)
                    mma_tf32(acc[mf][nf], a[mf], b0, b1);
            }
        }
    }

#pragma unroll
    for (int mf = 0; mf < 2; mf++) {
        const int r0 = bm + wm * 32 + mf * 16 + g;
#pragma unroll
        for (int nf = 0; nf < 8; nf++) {
            const int c0 = bn + wn * 64 + nf * 8 + t2;
            epi(r0,     c0,     acc[mf][nf][0]);
            epi(r0,     c0 + 1, acc[mf][nf][1]);
            epi(r0 + 8, c0,     acc[mf][nf][2]);
            epi(r0 + 8, c0 + 1, acc[mf][nf][3]);
        }
    }
}

__global__ __launch_bounds__(256) void qkv_mma_kernel(
    const float* __restrict__ x, const float* __restrict__ wq)
{
    QkvEpi epi;
    mma_gemm(x, wq, blockIdx.x * 128, blockIdx.y * 128, epi);
}

__global__ __launch_bounds__(256) void proj_mma_kernel(
    float* __restrict__ out, const float* __restrict__ bias,
    const float* __restrict__ wp)
{
    ProjEpi epi{out, bias};
    mma_gemm(g_att, wp, blockIdx.x * 128, blockIdx.y * 128, epi);
}

// ---------------------------------------------------------------------------
// TF32 flash attention: 4 warps x 32 q-rows (2 m-tiles), 64-key tiles,
// exp2 softmax, shuffle-remap PV (R14-validated). B-fragment LDS serves 2 mmas.
// ---------------------------------------------------------------------------
#define KTILE 64
#define KST 36    // sK row stride
#define VST 68    // sV row stride

__global__ __launch_bounds__(128) void attn_kernel(const void* __restrict__ kpm)
{
    __shared__ __align__(16) float sK[KTILE][KST];  // [key][dh]
    __shared__ __align__(16) float sV[32][VST];     // [dh][key]

    const int bh = blockIdx.y;
    const int b  = bh >> 3;
    const int h  = bh & 7;
    const int tid  = threadIdx.x;
    const int warp = tid >> 5;
    const int lane = tid & 31;
    const int g  = lane >> 2;
    const int tq = lane & 3;
    const int t2 = tq * 2;
    const int r0 = blockIdx.x * 128 + warp * 32;   // 32 rows per warp

    const int len = read_len(kpm, b);
    const float scale2 = 0.17677669529663687f * 1.4426950408889634f;

    // Q fragments: 2 m-tiles x 4 k8-steps x 4 regs
    float q[2][4][4];
    {
        const float* qb = g_q + ((size_t)bh * SEQ + r0) * DH;
#pragma unroll
        for (int mt = 0; mt < 2; mt++)
#pragma unroll
            for (int s = 0; s < 4; s++) {
                const int rb = mt * 16;
                q[mt][s][0] = qb[(size_t)(rb + g)     * DH + s*8 + tq];
                q[mt][s][1] = qb[(size_t)(rb + g + 8) * DH + s*8 + tq];
                q[mt][s][2] = qb[(size_t)(rb + g)     * DH + s*8 + tq + 4];
                q[mt][s][3] = qb[(size_t)(rb + g + 8) * DH + s*8 + tq + 4];
            }
    }

    float O[2][4][4];
#pragma unroll
    for (int mt = 0; mt < 2; mt++)
#pragma unroll
        for (int i = 0; i < 4; i++)
#pragma unroll
            for (int j = 0; j < 4; j++) O[mt][i][j] = 0.f;
    float m0[2] = {-CUDART_INF_F, -CUDART_INF_F};
    float m1[2] = {-CUDART_INF_F, -CUDART_INF_F};
    float l0[2] = {0.f, 0.f};
    float l1[2] = {0.f, 0.f};

    const int ntiles = (len + KTILE - 1) >> 6;
    for (int kt = 0; kt < ntiles; kt++) {
        const int k0 = kt * KTILE;
        __syncthreads();
        {
            const float* gk = g_k + ((size_t)bh * SEQ + k0) * DH;
            const float* gv = g_v + (size_t)bh * DH * SEQ + k0;
#pragma unroll
            for (int it = 0; it < 4; it++) {
                const int idx = tid + it * 128;        // 0..511
                const int krr = idx >> 3, kc = (idx & 7) * 4;
                *(float4*)&sK[krr][kc] = *(const float4*)(gk + (size_t)krr * DH + kc);
                const int vrr = idx >> 4, vc = (idx & 15) * 4;
                *(float4*)&sV[vrr][vc] = *(const float4*)(gv + (size_t)vrr * SEQ + vc);
            }
        }
        __syncthreads();

        // ---- S = Q K^T (32 x 64): each b-frag load feeds 2 mmas ----
        float S[2][8][4];
#pragma unroll
        for (int nt = 0; nt < 8; nt++) {
            S[0][nt][0] = S[0][nt][1] = S[0][nt][2] = S[0][nt][3] = 0.f;
            S[1][nt][0] = S[1][nt][1] = S[1][nt][2] = S[1][nt][3] = 0.f;
            const int key = nt * 8 + g;
#pragma unroll
            for (int ss = 0; ss < 4; ss++) {
                const float b0 = sK[key][ss*8 + tq];
                const float b1 = sK[key][ss*8 + tq + 4];
                mma_tf32(S[0][nt], q[0][ss], b0, b1);
                mma_tf32(S[1][nt], q[1][ss], b0, b1);
            }
        }

        // ---- scale (log2 domain) + mask ----
#pragma unroll
        for (int nt = 0; nt < 8; nt++) {
            const int kcol = k0 + nt * 8 + t2;
            const bool v0 = kcol < len, v1 = (kcol + 1) < len;
#pragma unroll
            for (int mt = 0; mt < 2; mt++) {
                S[mt][nt][0] = v0 ? S[mt][nt][0] * scale2 : -CUDART_INF_F;
                S[mt][nt][1] = v1 ? S[mt][nt][1] * scale2 : -CUDART_INF_F;
                S[mt][nt][2] = v0 ? S[mt][nt][2] * scale2 : -CUDART_INF_F;
                S[mt][nt][3] = v1 ? S[mt][nt][3] * scale2 : -CUDART_INF_F;
            }
        }

        // ---- online softmax per m-tile ----
#pragma unroll
        for (int mt = 0; mt < 2; mt++) {
            float rm0 = -CUDART_INF_F, rm1 = -CUDART_INF_F;
#pragma unroll
            for (int nt = 0; nt < 8; nt++) {
                rm0 = fmaxf(rm0, fmaxf(S[mt][nt][0], S[mt][nt][1]));
                rm1 = fmaxf(rm1, fmaxf(S[mt][nt][2], S[mt][nt][3]));
            }
            rm0 = fmaxf(rm0, __shfl_xor_sync(0xffffffffu, rm0, 1));
            rm0 = fmaxf(rm0, __shfl_xor_sync(0xffffffffu, rm0, 2));
            rm1 = fmaxf(rm1, __shfl_xor_sync(0xffffffffu, rm1, 1));
            rm1 = fmaxf(rm1, __shfl_xor_sync(0xffffffffu, rm1, 2));

            const float nm0 = fmaxf(m0[mt], rm0), nm1 = fmaxf(m1[mt], rm1);
            const float cr0 = exp2f(m0[mt] - nm0), cr1 = exp2f(m1[mt] - nm1);
            m0[mt] = nm0; m1[mt] = nm1;
            l0[mt] *= cr0; l1[mt] *= cr1;
#pragma unroll
            for (int dn = 0; dn < 4; dn++) {
                O[mt][dn][0] *= cr0; O[mt][dn][1] *= cr0;
                O[mt][dn][2] *= cr1; O[mt][dn][3] *= cr1;
            }

            float ps0 = 0.f, ps1 = 0.f;
#pragma unroll
            for (int nt = 0; nt < 8; nt++) {
                S[mt][nt][0] = exp2f(S[mt][nt][0] - nm0);
                S[mt][nt][1] = exp2f(S[mt][nt][1] - nm0);
                S[mt][nt][2] = exp2f(S[mt][nt][2] - nm1);
                S[mt][nt][3] = exp2f(S[mt][nt][3] - nm1);
                ps0 += S[mt][nt][0] + S[mt][nt][1];
                ps1 += S[mt][nt][2] + S[mt][nt][3];
            }
            ps0 += __shfl_xor_sync(0xffffffffu, ps0, 1);
            ps0 += __shfl_xor_sync(0xffffffffu, ps0, 2);
            ps1 += __shfl_xor_sync(0xffffffffu, ps1, 1);
            ps1 += __shfl_xor_sync(0xffffffffu, ps1, 2);
            l0[mt] += ps0; l1[mt] += ps1;
        }

        // ---- O += P V : quad-shuffle remap; each V b-frag feeds 2 mmas ----
        const int q0l = (lane & ~3) | (tq >> 1);
        const int q1l = q0l + 2;
        const bool odd = tq & 1;
#pragma unroll
        for (int ss = 0; ss < 8; ss++) {
            float a[2][4];
#pragma unroll
            for (int mt = 0; mt < 2; mt++) {
                const float v00 = __shfl_sync(0xffffffffu, S[mt][ss][0], q0l);
                const float v01 = __shfl_sync(0xffffffffu, S[mt][ss][1], q0l);
                const float v10 = __shfl_sync(0xffffffffu, S[mt][ss][2], q0l);
                const float v11 = __shfl_sync(0xffffffffu, S[mt][ss][3], q0l);
                const float w00 = __shfl_sync(0xffffffffu, S[mt][ss][0], q1l);
                const float w01 = __shfl_sync(0xffffffffu, S[mt][ss][1], q1l);
                const float w10 = __shfl_sync(0xffffffffu, S[mt][ss][2], q1l);
                const float w11 = __shfl_sync(0xffffffffu, S[mt][ss][3], q1l);
                a[mt][0] = tf32f(odd ? v01 : v00);
                a[mt][1] = tf32f(odd ? v11 : v10);
                a[mt][2] = tf32f(odd ? w01 : w00);
                a[mt][3] = tf32f(odd ? w11 : w10);
            }
#pragma unroll
            for (int dn = 0; dn < 4; dn++) {
                const float b0 = sV[dn*8 + g][ss*8 + tq];
                const float b1 = sV[dn*8 + g][ss*8 + tq + 4];
                mma_tf32(O[0][dn], a[0], b0, b1);
                mma_tf32(O[1][dn], a[1], b0, b1);
            }
        }
    }

    // ---- normalize + store (tf32-rounded for the proj GEMM) ----
#pragma unroll
    for (int mt = 0; mt < 2; mt++) {
        const float inv0 = 1.f / l0[mt], inv1 = 1.f / l1[mt];
        const int row0 = r0 + mt * 16 + g, row1 = row0 + 8;
#pragma unroll
        for (int dn = 0; dn < 4; dn++) {
            const int col = h * 32 + dn * 8 + t2;
            const size_t i0 = ((size_t)(b * SEQ + row0)) * CH + col;
            const size_t i1 = ((size_t)(b * SEQ + row1)) * CH + col;
            g_att[i0]     = tf32f(O[mt][dn][0] * inv0);
            g_att[i0 + 1] = tf32f(O[mt][dn][1] * inv0);
            g_att[i1]     = tf32f(O[mt][dn][2] * inv1);
            g_att[i1 + 1] = tf32f(O[mt][dn][3] * inv1);
        }
    }
}

// ---------------------------------------------------------------------------
// Launch
// ---------------------------------------------------------------------------
extern "C" void kernel_launch(void* const* d_in, const int* in_sizes, int n_in,
                              void* d_out, int out_size)
{
    (void)out_size;
    const float* x = nullptr; const void* kpm = nullptr;
    const float* w_qkv = nullptr; const float* w_proj = nullptr;
    const float* b_proj = nullptr;

    for (int i = 0; i < n_in; i++) {
        switch (in_sizes[i]) {
            case 2097152: x      = (const float*)d_in[i]; break;
            case 4:       kpm    = d_in[i];               break;
            case 196608:  w_qkv  = (const float*)d_in[i]; break;
            case 65536:   w_proj = (const float*)d_in[i]; break;
            case 256:     b_proj = (const float*)d_in[i]; break;
            default: break;
        }
    }
    float* out = (float*)d_out;

    {   // QKV mma: 8192 x 768 (rounding folded into g2s)
        dim3 grid(M_ROWS / 128, 768 / 128);
        qkv_mma_kernel<<<grid, 256>>>(x, w_qkv);
    }
    {   // attention: 128 q-rows per block (2 m-tiles/warp), 64-key tiles
        dim3 grid(SEQ / 128, BH);
        attn_kernel<<<grid, 128>>>(kpm);
    }
    {   // proj mma: 8192 x 256
        dim3 grid(M_ROWS / 128, 256 / 128);
        proj_mma_kernel<<<grid, 256>>>(out, b_proj, w_proj);
    }
}